// round 11
// baseline (speedup 1.0000x reference)
#include <cuda_runtime.h>
#include <math.h>

#define D_MODEL 1024
#define N_HEADS 16
#define K_WIN   8
#define BATCH   2
#define SEQ     2048
#define M_TOTAL (BATCH * SEQ)          // 4096 tokens
#define QKV_COLS (3 * D_MODEL)         // 3072

// Scratch (no cudaMalloc allowed): qkv projection + attention output.
// Referenced directly from device code — no host-side symbol lookup needed.
__device__ float g_qkv[(size_t)M_TOTAL * QKV_COLS];   // 50.3 MB
__device__ float g_att[(size_t)M_TOTAL * D_MODEL];    // 16.8 MB

// ---------------------------------------------------------------------------
// SGEMM: C[M,N] = A[M,K] @ W[N,K]^T + bias[N]
// 128x128 block tile, BK=32 (halved sync count vs R2), 256 threads, 8x8/thread.
// Identical register structure to the proven R2 kernel (121 regs @ occ 2).
// ---------------------------------------------------------------------------
#define BM 128
#define BN 128
#define BK 32

__device__ __forceinline__
void sgemm_body(const float* __restrict__ A,
                const float* __restrict__ W,
                const float* __restrict__ bias,
                float* __restrict__ C,
                int N, int K)
{
    __shared__ float As[BK][BM + 4];
    __shared__ float Bs[BK][BN + 4];

    const int tid = threadIdx.x;
    const int tx  = tid & 15;          // 0..15 -> N direction
    const int ty  = tid >> 4;          // 0..15 -> M direction
    const int bm  = blockIdx.y * BM;
    const int bn  = blockIdx.x * BN;

    const float* Ab = A + (size_t)bm * K;
    const float* Wb = W + (size_t)bn * K;

    float acc[8][8];
#pragma unroll
    for (int i = 0; i < 8; i++)
#pragma unroll
        for (int j = 0; j < 8; j++)
            acc[i][j] = 0.f;

    for (int k0 = 0; k0 < K; k0 += BK) {
        // Load 128x32 tiles of A and W, transposed into smem.
        // 1024 float4 per tile, 256 threads -> 4 each.
#pragma unroll
        for (int l = 0; l < 4; l++) {
            int idx = tid + l * 256;
            int row = idx >> 3;        // 0..127
            int c4  = (idx & 7) * 4;   // 0,4,...,28
            float4 va = *(const float4*)(Ab + (size_t)row * K + k0 + c4);
            As[c4 + 0][row] = va.x;
            As[c4 + 1][row] = va.y;
            As[c4 + 2][row] = va.z;
            As[c4 + 3][row] = va.w;
            float4 vb = *(const float4*)(Wb + (size_t)row * K + k0 + c4);
            Bs[c4 + 0][row] = vb.x;
            Bs[c4 + 1][row] = vb.y;
            Bs[c4 + 2][row] = vb.z;
            Bs[c4 + 3][row] = vb.w;
        }
        __syncthreads();

#pragma unroll
        for (int kk = 0; kk < BK; kk++) {
            float4 a0 = *(const float4*)&As[kk][ty * 8];
            float4 a1 = *(const float4*)&As[kk][ty * 8 + 4];
            float4 b0 = *(const float4*)&Bs[kk][tx * 8];
            float4 b1 = *(const float4*)&Bs[kk][tx * 8 + 4];
            float a[8] = {a0.x, a0.y, a0.z, a0.w, a1.x, a1.y, a1.z, a1.w};
            float b[8] = {b0.x, b0.y, b0.z, b0.w, b1.x, b1.y, b1.z, b1.w};
#pragma unroll
            for (int i = 0; i < 8; i++)
#pragma unroll
                for (int j = 0; j < 8; j++)
                    acc[i][j] = fmaf(a[i], b[j], acc[i][j]);
        }
        __syncthreads();
    }

    float4 bia0 = *(const float4*)(bias + bn + tx * 8);
    float4 bia1 = *(const float4*)(bias + bn + tx * 8 + 4);
    float bb[8] = {bia0.x, bia0.y, bia0.z, bia0.w, bia1.x, bia1.y, bia1.z, bia1.w};

#pragma unroll
    for (int i = 0; i < 8; i++) {
        int gm = bm + ty * 8 + i;
        float* Crow = C + (size_t)gm * N + bn + tx * 8;
        float4 o0 = make_float4(acc[i][0] + bb[0], acc[i][1] + bb[1],
                                acc[i][2] + bb[2], acc[i][3] + bb[3]);
        float4 o1 = make_float4(acc[i][4] + bb[4], acc[i][5] + bb[5],
                                acc[i][6] + bb[6], acc[i][7] + bb[7]);
        *(float4*)(Crow)     = o0;
        *(float4*)(Crow + 4) = o1;
    }
}

__global__ __launch_bounds__(256, 2)
void sgemm_x_to_qkv(const float* __restrict__ x,
                    const float* __restrict__ qkv_w,
                    const float* __restrict__ qkv_b)
{
    sgemm_body(x, qkv_w, qkv_b, g_qkv, QKV_COLS, D_MODEL);
}

__global__ __launch_bounds__(256, 2)
void sgemm_att_to_out(const float* __restrict__ out_w,
                      const float* __restrict__ out_b,
                      float* __restrict__ out)
{
    sgemm_body(g_att, out_w, out_b, out, D_MODEL, D_MODEL);
}

// ---------------------------------------------------------------------------
// QK-norm: L2-normalize each 64-element head vector of q and k (in place).
// One warp per segment: M_TOTAL tokens * 32 segments (16 q-heads + 16 k-heads)
// ---------------------------------------------------------------------------
__global__ void qknorm_kernel()
{
    int gw   = (blockIdx.x * blockDim.x + threadIdx.x) >> 5;
    int lane = threadIdx.x & 31;
    if (gw >= M_TOTAL * 32) return;
    int row = gw >> 5;         // token
    int seg = gw & 31;         // 0..15 q heads, 16..31 k heads
    size_t off = (size_t)row * QKV_COLS +
                 (seg < 16 ? seg * 64 : D_MODEL + (seg - 16) * 64);
    float* p = g_qkv + off;
    float2 v = *(float2*)(p + lane * 2);
    float ss = v.x * v.x + v.y * v.y;
#pragma unroll
    for (int o = 16; o; o >>= 1) ss += __shfl_xor_sync(0xFFFFFFFFu, ss, o);
    float inv = 1.0f / (sqrtf(ss) + 1e-6f);
    v.x *= inv; v.y *= inv;
    *(float2*)(p + lane * 2) = v;
}

// ---------------------------------------------------------------------------
// Dilated attention: one warp per (token, head).
// Window: j = i + 2*(t-8), t in [0,17), clipped to [0,SEQ). scale = 1.0
// ---------------------------------------------------------------------------
__global__ void attend_kernel()
{
    int gw   = (blockIdx.x * blockDim.x + threadIdx.x) >> 5;
    int lane = threadIdx.x & 31;
    if (gw >= M_TOTAL * N_HEADS) return;
    int r = gw >> 4;           // token index 0..4095
    int h = gw & 15;
    int b = r / SEQ;
    int i = r % SEQ;

    const float* qp = g_qkv + (size_t)r * QKV_COLS + h * 64;
    const float* kb = g_qkv + (size_t)(b * SEQ) * QKV_COLS + D_MODEL + h * 64;
    const float* vb = g_qkv + (size_t)(b * SEQ) * QKV_COLS + 2 * D_MODEL + h * 64;

    float2 q = *(const float2*)(qp + lane * 2);

    float sc[17];
#pragma unroll
    for (int t = 0; t < 17; t++) {
        int j = i + 2 * (t - K_WIN);
        float s = -INFINITY;
        if (j >= 0 && j < SEQ) {
            float2 k = *(const float2*)(kb + (size_t)j * QKV_COLS + lane * 2);
            float d = q.x * k.x + q.y * k.y;
#pragma unroll
            for (int o = 16; o; o >>= 1) d += __shfl_xor_sync(0xFFFFFFFFu, d, o);
            s = d;
        }
        sc[t] = s;
    }

    float mx = -INFINITY;
#pragma unroll
    for (int t = 0; t < 17; t++) mx = fmaxf(mx, sc[t]);
    float den = 0.f;
#pragma unroll
    for (int t = 0; t < 17; t++) {
        float e = (sc[t] == -INFINITY) ? 0.f : __expf(sc[t] - mx);
        sc[t] = e;
        den += e;
    }
    float inv = 1.0f / den;   // den >= 1: j=i always valid -> exp(0) term present

    float2 acc = make_float2(0.f, 0.f);
#pragma unroll
    for (int t = 0; t < 17; t++) {
        int j = i + 2 * (t - K_WIN);
        if (j >= 0 && j < SEQ) {
            float2 v = *(const float2*)(vb + (size_t)j * QKV_COLS + lane * 2);
            float p = sc[t] * inv;
            acc.x = fmaf(p, v.x, acc.x);
            acc.y = fmaf(p, v.y, acc.y);
        }
    }
    *(float2*)(g_att + (size_t)r * D_MODEL + h * 64 + lane * 2) = acc;
}

// ---------------------------------------------------------------------------
// Launch: pure kernel launches, nothing else (graph-capture safe).
// ---------------------------------------------------------------------------
extern "C" void kernel_launch(void* const* d_in, const int* in_sizes, int n_in,
                              void* d_out, int out_size)
{
    const float* x     = (const float*)d_in[0];
    const float* qkv_w = (const float*)d_in[1];
    const float* qkv_b = (const float*)d_in[2];
    const float* out_w = (const float*)d_in[3];
    const float* out_b = (const float*)d_in[4];
    float* out = (float*)d_out;

    // 1) QKV projection: (4096,1024) @ (3072,1024)^T -> g_qkv (4096,3072)
    {
        dim3 grid(QKV_COLS / BN, M_TOTAL / BM);
        sgemm_x_to_qkv<<<grid, 256>>>(x, qkv_w, qkv_b);
    }

    // 2) QK L2-normalization (in place on g_qkv)
    qknorm_kernel<<<(M_TOTAL * 32) / 8, 256>>>();

    // 3) Dilated windowed attention -> g_att
    attend_kernel<<<(M_TOTAL * N_HEADS) / 8, 256>>>();

    // 4) Output projection: g_att (4096,1024) @ (1024,1024)^T -> out
    {
        dim3 grid(D_MODEL / BN, M_TOTAL / BM);
        sgemm_att_to_out<<<grid, 256>>>(out_w, out_b, out);
    }
}

// round 12
// speedup vs baseline: 1.6391x; 1.6391x over previous
#include <cuda_runtime.h>
#include <math.h>
#include <stdint.h>

#define D_MODEL 1024
#define N_HEADS 16
#define K_WIN   8
#define BATCH   2
#define SEQ     2048
#define M_TOTAL (BATCH * SEQ)          // 4096 tokens
#define QKV_COLS (3 * D_MODEL)         // 3072

// Scratch (no cudaMalloc allowed): qkv projection + attention output.
__device__ float g_qkv[(size_t)M_TOTAL * QKV_COLS];   // 50.3 MB
__device__ float g_att[(size_t)M_TOTAL * D_MODEL];    // 16.8 MB

// ---------------------------------------------------------------------------
// tf32 helpers: x = hi + lo, both exactly representable in tf32.
// hi/lo are stored interleaved along K in smem -> a plain tf32 GEMM over
// K' = 2K reproduces the fp32 product to ~2^-21 relative error.
// ---------------------------------------------------------------------------
__device__ __forceinline__ uint32_t f2tf(float x) {
    uint32_t r;
    asm("cvt.rna.tf32.f32 %0, %1;" : "=r"(r) : "f"(x));
    return r;
}
__device__ __forceinline__ void tfpair(float x, uint32_t& hi, uint32_t& lo) {
    hi = f2tf(x);
    lo = f2tf(x - __uint_as_float(hi));
}

// ---------------------------------------------------------------------------
// tf32 mma.sync GEMM: C[M,N] = A[M,K]fp32 @ W[N,K]fp32^T + bias (fp32 out)
// CTA tile 128x128, 256 threads / 8 warps (warp tile 64x32, 64 fp32 accs —
// the register structure R11 proved clean at 127 regs).
// Per chunk: 16 fp32 K-cols are loaded, split to 32 interleaved tf32 cols
// in smem, then consumed by 4 k-steps of m16n8k8. 64 chunks (K=1024).
// ---------------------------------------------------------------------------
#define BM   128
#define BN   128
#define PADT 36              // smem row: 32 tf32 + 4 pad words (144 B)

__device__ __forceinline__
void tf32_gemm_body(const float* __restrict__ A,
                    const float* __restrict__ W,
                    const float* __restrict__ bias,
                    float* __restrict__ C,
                    int N, int K)
{
    __shared__ uint32_t As[BM][PADT];
    __shared__ uint32_t Bs[BN][PADT];

    const int tid    = threadIdx.x;
    const int wid    = tid >> 5;
    const int lane   = tid & 31;
    const int g      = lane >> 2;      // group 0..7
    const int t      = lane & 3;       // thread-in-group
    const int warp_m = wid & 1;        // 0..1 (64-row slabs)
    const int warp_n = wid >> 1;       // 0..3 (32-col slabs)

    const int bm = blockIdx.y * BM;
    const int bn = blockIdx.x * BN;
    const float* Arow = A + (size_t)bm * K;
    const float* Wrow = W + (size_t)bn * K;

    // Loader: 512 float4-chunks per operand tile (128 rows x 16 fp32 cols);
    // thread handles chunks tid and tid+256.
    const int r0 = tid >> 2,         c40 = (tid & 3) * 4;
    const int r1 = (tid + 256) >> 2, c41 = ((tid + 256) & 3) * 4;

    float acc[4][4][4];
#pragma unroll
    for (int i = 0; i < 4; i++)
#pragma unroll
        for (int j = 0; j < 4; j++)
#pragma unroll
            for (int e = 0; e < 4; e++) acc[i][j][e] = 0.f;

    const int NITER = K / 16;     // 64

    for (int c = 0; c < NITER; c++) {
        const int k0 = c * 16;
        // Load 16 fp32 cols, split to 32 interleaved tf32 cols in smem.
#pragma unroll
        for (int l = 0; l < 2; l++) {
            const int row = l ? r1 : r0;
            const int c4  = l ? c41 : c40;
            {
                float4 v = *(const float4*)(Arow + (size_t)row * K + k0 + c4);
                uint4 h0, h1;
                tfpair(v.x, h0.x, h0.y);
                tfpair(v.y, h0.z, h0.w);
                tfpair(v.z, h1.x, h1.y);
                tfpair(v.w, h1.z, h1.w);
                *(uint4*)&As[row][2 * c4]     = h0;
                *(uint4*)&As[row][2 * c4 + 4] = h1;
            }
            {
                float4 v = *(const float4*)(Wrow + (size_t)row * K + k0 + c4);
                uint4 h0, h1;
                tfpair(v.x, h0.x, h0.y);
                tfpair(v.y, h0.z, h0.w);
                tfpair(v.z, h1.x, h1.y);
                tfpair(v.w, h1.z, h1.w);
                *(uint4*)&Bs[row][2 * c4]     = h0;
                *(uint4*)&Bs[row][2 * c4 + 4] = h1;
            }
        }
        __syncthreads();

#pragma unroll
        for (int s = 0; s < 4; s++) {
            const int kb = s * 8;
            // B fragments: b0 = B[n][kb+t], b1 = B[n][kb+t+4]
            const uint32_t b00 = Bs[warp_n * 32 + 0 * 8 + g][kb + t];
            const uint32_t b01 = Bs[warp_n * 32 + 0 * 8 + g][kb + t + 4];
            const uint32_t b10 = Bs[warp_n * 32 + 1 * 8 + g][kb + t];
            const uint32_t b11 = Bs[warp_n * 32 + 1 * 8 + g][kb + t + 4];
            const uint32_t b20 = Bs[warp_n * 32 + 2 * 8 + g][kb + t];
            const uint32_t b21 = Bs[warp_n * 32 + 2 * 8 + g][kb + t + 4];
            const uint32_t b30 = Bs[warp_n * 32 + 3 * 8 + g][kb + t];
            const uint32_t b31 = Bs[warp_n * 32 + 3 * 8 + g][kb + t + 4];
#pragma unroll
            for (int mf = 0; mf < 4; mf++) {
                const int mr = warp_m * 64 + mf * 16;
                const uint32_t a0 = As[mr + g    ][kb + t];
                const uint32_t a1 = As[mr + g + 8][kb + t];
                const uint32_t a2 = As[mr + g    ][kb + t + 4];
                const uint32_t a3 = As[mr + g + 8][kb + t + 4];
#define TF32_MMA(nf, bb0, bb1)                                          \
                asm volatile(                                           \
                    "mma.sync.aligned.m16n8k8.row.col.f32.tf32.tf32.f32 " \
                    "{%0,%1,%2,%3}, {%4,%5,%6,%7}, {%8,%9}, {%0,%1,%2,%3};" \
                    : "+f"(acc[mf][nf][0]), "+f"(acc[mf][nf][1]),       \
                      "+f"(acc[mf][nf][2]), "+f"(acc[mf][nf][3])        \
                    : "r"(a0), "r"(a1), "r"(a2), "r"(a3), "r"(bb0), "r"(bb1))
                TF32_MMA(0, b00, b01);
                TF32_MMA(1, b10, b11);
                TF32_MMA(2, b20, b21);
                TF32_MMA(3, b30, b31);
#undef TF32_MMA
            }
        }
        __syncthreads();
    }

    // Epilogue: acc e0,e1 -> (row g, cols 2t,2t+1); e2,e3 -> (row g+8).
#pragma unroll
    for (int mf = 0; mf < 4; mf++) {
        const int gr = bm + warp_m * 64 + mf * 16 + g;
#pragma unroll
        for (int nf = 0; nf < 4; nf++) {
            const int gc = bn + warp_n * 32 + nf * 8 + t * 2;
            const float b0 = __ldg(bias + gc);
            const float b1 = __ldg(bias + gc + 1);
            float2 v0 = make_float2(acc[mf][nf][0] + b0, acc[mf][nf][1] + b1);
            float2 v1 = make_float2(acc[mf][nf][2] + b0, acc[mf][nf][3] + b1);
            *(float2*)(C + (size_t)gr * N + gc)       = v0;
            *(float2*)(C + (size_t)(gr + 8) * N + gc) = v1;
        }
    }
}

__global__ __launch_bounds__(256)
void tf32_x_to_qkv(const float* __restrict__ x,
                   const float* __restrict__ qkv_w,
                   const float* __restrict__ qkv_b)
{
    tf32_gemm_body(x, qkv_w, qkv_b, g_qkv, QKV_COLS, D_MODEL);
}

__global__ __launch_bounds__(256)
void tf32_att_to_out(const float* __restrict__ out_w,
                     const float* __restrict__ out_b,
                     float* __restrict__ out)
{
    tf32_gemm_body(g_att, out_w, out_b, out, D_MODEL, D_MODEL);
}

// ---------------------------------------------------------------------------
// QK-norm: L2-normalize each 64-element head vector of q and k (in place).
// (byte-identical to the R11-proven version)
// ---------------------------------------------------------------------------
__global__ void qknorm_kernel()
{
    int gw   = (blockIdx.x * blockDim.x + threadIdx.x) >> 5;
    int lane = threadIdx.x & 31;
    if (gw >= M_TOTAL * 32) return;
    int row = gw >> 5;         // token
    int seg = gw & 31;         // 0..15 q heads, 16..31 k heads
    size_t off = (size_t)row * QKV_COLS +
                 (seg < 16 ? seg * 64 : D_MODEL + (seg - 16) * 64);
    float* p = g_qkv + off;
    float2 v = *(float2*)(p + lane * 2);
    float ss = v.x * v.x + v.y * v.y;
#pragma unroll
    for (int o = 16; o; o >>= 1) ss += __shfl_xor_sync(0xFFFFFFFFu, ss, o);
    float inv = 1.0f / (sqrtf(ss) + 1e-6f);
    v.x *= inv; v.y *= inv;
    *(float2*)(p + lane * 2) = v;
}

// ---------------------------------------------------------------------------
// Dilated attention: one warp per (token, head).
// (byte-identical to the R11-proven version)
// ---------------------------------------------------------------------------
__global__ void attend_kernel()
{
    int gw   = (blockIdx.x * blockDim.x + threadIdx.x) >> 5;
    int lane = threadIdx.x & 31;
    if (gw >= M_TOTAL * N_HEADS) return;
    int r = gw >> 4;           // token index 0..4095
    int h = gw & 15;
    int b = r / SEQ;
    int i = r % SEQ;

    const float* qp = g_qkv + (size_t)r * QKV_COLS + h * 64;
    const float* kb = g_qkv + (size_t)(b * SEQ) * QKV_COLS + D_MODEL + h * 64;
    const float* vb = g_qkv + (size_t)(b * SEQ) * QKV_COLS + 2 * D_MODEL + h * 64;

    float2 q = *(const float2*)(qp + lane * 2);

    float sc[17];
#pragma unroll
    for (int t = 0; t < 17; t++) {
        int j = i + 2 * (t - K_WIN);
        float s = -INFINITY;
        if (j >= 0 && j < SEQ) {
            float2 k = *(const float2*)(kb + (size_t)j * QKV_COLS + lane * 2);
            float d = q.x * k.x + q.y * k.y;
#pragma unroll
            for (int o = 16; o; o >>= 1) d += __shfl_xor_sync(0xFFFFFFFFu, d, o);
            s = d;
        }
        sc[t] = s;
    }

    float mx = -INFINITY;
#pragma unroll
    for (int t = 0; t < 17; t++) mx = fmaxf(mx, sc[t]);
    float den = 0.f;
#pragma unroll
    for (int t = 0; t < 17; t++) {
        float e = (sc[t] == -INFINITY) ? 0.f : __expf(sc[t] - mx);
        sc[t] = e;
        den += e;
    }
    float inv = 1.0f / den;   // den >= 1: j=i always valid -> exp(0) term present

    float2 acc = make_float2(0.f, 0.f);
#pragma unroll
    for (int t = 0; t < 17; t++) {
        int j = i + 2 * (t - K_WIN);
        if (j >= 0 && j < SEQ) {
            float2 v = *(const float2*)(vb + (size_t)j * QKV_COLS + lane * 2);
            float p = sc[t] * inv;
            acc.x = fmaf(p, v.x, acc.x);
            acc.y = fmaf(p, v.y, acc.y);
        }
    }
    *(float2*)(g_att + (size_t)r * D_MODEL + h * 64 + lane * 2) = acc;
}

// ---------------------------------------------------------------------------
// Launch: pure kernel launches, nothing else (graph-capture safe).
// ---------------------------------------------------------------------------
extern "C" void kernel_launch(void* const* d_in, const int* in_sizes, int n_in,
                              void* d_out, int out_size)
{
    const float* x     = (const float*)d_in[0];
    const float* qkv_w = (const float*)d_in[1];
    const float* qkv_b = (const float*)d_in[2];
    const float* out_w = (const float*)d_in[3];
    const float* out_b = (const float*)d_in[4];
    float* out = (float*)d_out;

    // 1) QKV projection: (4096,1024) @ (3072,1024)^T -> g_qkv (4096,3072)
    {
        dim3 grid(QKV_COLS / BN, M_TOTAL / BM);
        tf32_x_to_qkv<<<grid, 256>>>(x, qkv_w, qkv_b);
    }

    // 2) QK L2-normalization (in place on g_qkv)
    qknorm_kernel<<<(M_TOTAL * 32) / 8, 256>>>();

    // 3) Dilated windowed attention -> g_att
    attend_kernel<<<(M_TOTAL * N_HEADS) / 8, 256>>>();

    // 4) Output projection: g_att (4096,1024) @ (1024,1024)^T -> out
    {
        dim3 grid(D_MODEL / BN, M_TOTAL / BM);
        tf32_att_to_out<<<grid, 256>>>(out_w, out_b, out);
    }
}